// round 13
// baseline (speedup 1.0000x reference)
#include <cuda_runtime.h>

// Haar DWT: x (8, 4096, 1024) fp32 -> cA, cD each (8, 2048, 1024)
// cA = (x_even + x_odd) * INV_SQRT2 ; cD = (x_even - x_odd) * INV_SQRT2
// d_out = [cA | cD].
//
// R12 (= R11 resubmit after infra failure): persistent one-wave variant of
// the roofline kernel. grid = 148 SMs x 8 CTAs = 1184 blocks, each
// grid-striding over the 2,097,152 work items (2 float4-pairs per item).
// Eliminates ~7 wave transitions and keeps each SM's load stream continuous
// across iterations (loads of iter k+1 issue while stores of iter k drain).
// Same irreducible 268 MB DRAM stream.

#define INV_SQRT2F 0.70710678118654752440f

__global__ void __launch_bounds__(256) dwt_haar_kernel(
    const float4* __restrict__ x,
    float4* __restrict__ out,
    int n4_out,   // float4s per output tensor (4,194,304)
    int nwork)    // work items = n4_out/2 (2,097,152)
{
    const int stride = gridDim.x * blockDim.x;   // 303,104
    for (int i = blockIdx.x * blockDim.x + threadIdx.x; i < nwork; i += stride) {
        int pair = i >> 7;        // (b*2048 + row) pair index
        int d4   = i & 127;       // float4 column (first half of row)

        int e = pair * 512 + d4;  // even-row float4 base; odd row = +256

        float4 a0 = __ldcs(&x[e]);
        float4 a1 = __ldcs(&x[e + 128]);
        float4 b0 = __ldcs(&x[e + 256]);
        float4 b1 = __ldcs(&x[e + 384]);

        float4 cA0, cD0, cA1, cD1;
        cA0.x = (a0.x + b0.x) * INV_SQRT2F;  cD0.x = (a0.x - b0.x) * INV_SQRT2F;
        cA0.y = (a0.y + b0.y) * INV_SQRT2F;  cD0.y = (a0.y - b0.y) * INV_SQRT2F;
        cA0.z = (a0.z + b0.z) * INV_SQRT2F;  cD0.z = (a0.z - b0.z) * INV_SQRT2F;
        cA0.w = (a0.w + b0.w) * INV_SQRT2F;  cD0.w = (a0.w - b0.w) * INV_SQRT2F;

        cA1.x = (a1.x + b1.x) * INV_SQRT2F;  cD1.x = (a1.x - b1.x) * INV_SQRT2F;
        cA1.y = (a1.y + b1.y) * INV_SQRT2F;  cD1.y = (a1.y - b1.y) * INV_SQRT2F;
        cA1.z = (a1.z + b1.z) * INV_SQRT2F;  cD1.z = (a1.z - b1.z) * INV_SQRT2F;
        cA1.w = (a1.w + b1.w) * INV_SQRT2F;  cD1.w = (a1.w - b1.w) * INV_SQRT2F;

        int o = pair * 256 + d4;
        __stcs(&out[o],                 cA0);
        __stcs(&out[o + 128],           cA1);
        __stcs(&out[n4_out + o],        cD0);
        __stcs(&out[n4_out + o + 128],  cD1);
    }
}

extern "C" void kernel_launch(void* const* d_in, const int* in_sizes, int n_in,
                              void* d_out, int out_size)
{
    const float4* x = (const float4*)d_in[0];
    float4* out     = (float4*)d_out;

    int n4_out = (out_size / 2) / 4;   // 4,194,304
    int nwork  = n4_out / 2;           // 2,097,152

    const int threads = 256;
    const int blocks  = 148 * 8;       // one full wave at occ 8

    dwt_haar_kernel<<<blocks, threads>>>(x, out, n4_out, nwork);
}

// round 17
// speedup vs baseline: 1.0920x; 1.0920x over previous
#include <cuda_runtime.h>

// Haar DWT: x (8, 4096, 1024) fp32 -> cA, cD each (8, 2048, 1024)
// cA = (x_even + x_odd) * INV_SQRT2 ; cD = (x_even - x_odd) * INV_SQRT2
// d_out = [cA | cD].
//
// FINAL (best measured config, 43.5 us): flat one-shot launch, 2 float4-pairs
// per thread (cols d4 and d4+128 of the same row pair), 4 independent
// streaming loads front-batched per thread, fully coalesced, __stcs
// write-back streaming stores. Sits at the HBM mixed r/w roofline
// (~6.1 TB/s steady for the irreducible 268 MB stream).
//
// Tested and rejected: write-through stores (regress), L2 evict_last/-first
// residency pinning full & partial (neutral -- no cross-replay residency on
// this part), persistent one-wave grid-stride (regress -- loop back-edge
// serializes load issue vs. flat launch's cross-CTA overlap).

#define INV_SQRT2F 0.70710678118654752440f

__global__ void __launch_bounds__(256) dwt_haar_kernel(
    const float4* __restrict__ x,
    float4* __restrict__ out,
    int n4_out)  // float4s per output tensor (4,194,304)
{
    int i = blockIdx.x * blockDim.x + threadIdx.x;   // n4_out/2 threads
    int pair = i >> 7;        // (b*2048 + row) pair index
    int d4   = i & 127;       // float4 column (first half of 256-wide row)

    int e = pair * 512 + d4;  // even-row float4 base; odd row = +256

    // 4 independent loads, front-batched
    float4 a0 = __ldcs(&x[e]);
    float4 a1 = __ldcs(&x[e + 128]);
    float4 b0 = __ldcs(&x[e + 256]);
    float4 b1 = __ldcs(&x[e + 384]);

    float4 cA0, cD0, cA1, cD1;
    cA0.x = (a0.x + b0.x) * INV_SQRT2F;  cD0.x = (a0.x - b0.x) * INV_SQRT2F;
    cA0.y = (a0.y + b0.y) * INV_SQRT2F;  cD0.y = (a0.y - b0.y) * INV_SQRT2F;
    cA0.z = (a0.z + b0.z) * INV_SQRT2F;  cD0.z = (a0.z - b0.z) * INV_SQRT2F;
    cA0.w = (a0.w + b0.w) * INV_SQRT2F;  cD0.w = (a0.w - b0.w) * INV_SQRT2F;

    cA1.x = (a1.x + b1.x) * INV_SQRT2F;  cD1.x = (a1.x - b1.x) * INV_SQRT2F;
    cA1.y = (a1.y + b1.y) * INV_SQRT2F;  cD1.y = (a1.y - b1.y) * INV_SQRT2F;
    cA1.z = (a1.z + b1.z) * INV_SQRT2F;  cD1.z = (a1.z - b1.z) * INV_SQRT2F;
    cA1.w = (a1.w + b1.w) * INV_SQRT2F;  cD1.w = (a1.w - b1.w) * INV_SQRT2F;

    int o = pair * 256 + d4;  // output float4 index within cA
    __stcs(&out[o],                 cA0);
    __stcs(&out[o + 128],           cA1);
    __stcs(&out[n4_out + o],        cD0);
    __stcs(&out[n4_out + o + 128],  cD1);
}

extern "C" void kernel_launch(void* const* d_in, const int* in_sizes, int n_in,
                              void* d_out, int out_size)
{
    const float4* x = (const float4*)d_in[0];
    float4* out     = (float4*)d_out;

    int n4_out  = (out_size / 2) / 4;   // 4,194,304
    int threadsTotal = n4_out / 2;      // 2,097,152

    const int threads = 256;
    int blocks = threadsTotal / threads;  // 8192

    dwt_haar_kernel<<<blocks, threads>>>(x, out, n4_out);
}